// round 14
// baseline (speedup 1.0000x reference)
#include <cuda_runtime.h>
#include <cuda_fp16.h>
#include <cstdint>

// TpsGridGen: theta (64,50) -> grid (64,256,192,2) fp32
// R14: mma.sync.m16n8k8, parallelism-tuned.
//   Block = 256 thr (8 warps) x 128 px x all 64 batches. Grid = 384.
//   Warp = 16 px x 128 n (16 n-tiles). A frags loaded once.
//   3 hi/lo passes get SEPARATE accumulator sets (chain depth 4, ILP 3),
//   merged by FADD. Phase A (C solve, tid<128) || U build (tid>=128).

#define OUT_H 256
#define OUT_W 192
#define NPX   (OUT_H * OUT_W)
#define NCP   25
#define NK    28
#define PXB   128     // pixels per block
#define NTHR  256

__host__ __device__ constexpr float cpx(int n) { return 0.5f * (float)(n / 5) - 1.0f; }
__host__ __device__ constexpr float cpy(int n) { return 0.5f * (float)(n % 5) - 1.0f; }

// ---------------------------------------------------------------------------
// Compile-time inv(L), transposed to [m][k], RBF rows (k<25) pre-scaled by ln2
// ---------------------------------------------------------------------------
constexpr double cfabs(double x) { return x < 0.0 ? -x : x; }

constexpr double clog(double x) {
    int e = 0;
    while (x >= 1.4142135623730951) { x *= 0.5; e++; }
    while (x <  0.7071067811865476) { x *= 2.0; e--; }
    double t = (x - 1.0) / (x + 1.0), t2 = t * t, p = t, s = 0.0;
    for (int k = 0; k < 27; k++) { s += p / (double)(2 * k + 1); p *= t2; }
    return 2.0 * s + (double)e * 0.6931471805599453094172321214581766;
}

struct alignas(16) TPSLiS { float v[NCP][NK]; };   // [m][k]

constexpr TPSLiS make_lis() {
    const double ax[5] = {-1.0, -0.5, 0.0, 0.5, 1.0};
    double PX[NCP] = {}, PY[NCP] = {};
    for (int i = 0; i < 5; i++)
        for (int j = 0; j < 5; j++) { PX[i*5+j] = ax[i]; PY[i*5+j] = ax[j]; }

    double a[28][56] = {};
    for (int i = 0; i < 25; i++)
        for (int j = 0; j < 25; j++)
            if (i != j) {
                double dx = PX[i]-PX[j], dy = PY[i]-PY[j];
                double d2 = dx*dx + dy*dy;
                a[i][j] = d2 * clog(d2);
            }
    for (int i = 0; i < 25; i++) {
        a[i][25] = 1.0; a[i][26] = PX[i]; a[i][27] = PY[i];
        a[25][i] = 1.0; a[26][i] = PX[i]; a[27][i] = PY[i];
    }
    for (int i = 0; i < 28; i++) a[i][28+i] = 1.0;

    for (int k = 0; k < 28; k++) {
        int piv = k; double best = cfabs(a[k][k]);
        for (int i = k+1; i < 28; i++) {
            double v = cfabs(a[i][k]);
            if (v > best) { best = v; piv = i; }
        }
        if (piv != k)
            for (int j = 0; j < 56; j++) {
                double t = a[k][j]; a[k][j] = a[piv][j]; a[piv][j] = t;
            }
        double inv = 1.0 / a[k][k];
        for (int j = 0; j < 56; j++) a[k][j] *= inv;
        for (int i = 0; i < 28; i++) {
            if (i == k) continue;
            double f = a[i][k];
            if (f != 0.0)
                for (int j = 0; j < 56; j++) a[i][j] -= f * a[k][j];
        }
    }
    const double LN2 = 0.6931471805599453094172321214581766;
    TPSLiS r{};
    for (int m = 0; m < NCP; m++)
        for (int k = 0; k < NK; k++)
            r.v[m][k] = (float)(((k < 25) ? LN2 : 1.0) * a[k][28 + m]);
    return r;
}

__device__ const TPSLiS g_lis = make_lis();

// Compile-time linspace tables (numpy fp64 semantics, endpoint exact).
struct alignas(16) GridTab { float g[448]; };   // [0..191]=gx, [192..447]=gy

constexpr GridTab make_grid() {
    GridTab r{};
    for (int w = 0; w < OUT_W; w++)
        r.g[w] = (float)(-1.0 + (double)w * (2.0 / (double)(OUT_W - 1)));
    r.g[OUT_W - 1] = 1.0f;
    for (int h = 0; h < OUT_H; h++)
        r.g[192 + h] = (float)(-1.0 + (double)h * (2.0 / (double)(OUT_H - 1)));
    r.g[192 + OUT_H - 1] = 1.0f;
    return r;
}

__device__ const GridTab g_grid = make_grid();

// ---------------------------------------------------------------------------
__device__ __forceinline__ uint32_t h2bits(__half2 h) {
    return *reinterpret_cast<uint32_t*>(&h);
}

__device__ __forceinline__ void hilo(float v0, float v1, uint32_t& hi, uint32_t& lo) {
    __half2 h = __floats2half2_rn(v0, v1);
    float r0 = v0 - __low2float(h);
    float r1 = v1 - __high2float(h);
    hi = h2bits(h);
    lo = h2bits(__floats2half2_rn(r0, r1));
}

__device__ __forceinline__ void mma16n8k8(float& d0, float& d1, float& d2, float& d3,
                                          uint32_t a0, uint32_t a1, uint32_t b0) {
    asm("mma.sync.aligned.m16n8k8.row.col.f32.f16.f16.f32 "
        "{%0,%1,%2,%3},{%4,%5},{%6},{%0,%1,%2,%3};"
        : "+f"(d0), "+f"(d1), "+f"(d2), "+f"(d3)
        : "r"(a0), "r"(a1), "r"(b0));
}

// ---------------------------------------------------------------------------
// Kernel. grid 384, block 256. Block = 128 px x 64 batches (128 n-rows).
// Warp = 16 px x 128 n.
// ---------------------------------------------------------------------------
__global__ __launch_bounds__(NTHR) void tps_mma_kernel(
    const float* __restrict__ theta, float2* __restrict__ out) {

    __shared__ __align__(16) float    s_li[NCP * NK];        // 2.8 KB
    __shared__ uint32_t s_uh[PXB][16], s_ul[PXB][16];        // 16 KB
    __shared__ uint32_t s_ch[128][16], s_cl[128][16];        // 16 KB

    const int tid = threadIdx.x;
    const int wid = tid >> 5;
    const int lid = tid & 31;

    // ---- Stage Li (175 f4) ----
    {
        const float4* ls = (const float4*)&g_lis;
        for (int i = tid; i < 175; i += NTHR) ((float4*)s_li)[i] = ls[i];
    }
    __syncthreads();

    if (tid < 128) {
        // ---- Phase A: thread = n-row (n = 2b+axis), theta from L2 ----
        const int b    = tid >> 1;
        const int axis = tid & 1;
        const float* trow = theta + b * 50 + axis * NCP;
        float acc[NK];
#pragma unroll
        for (int k = 0; k < NK; k++) acc[k] = 0.f;
#pragma unroll
        for (int m = 0; m < NCP; m++) {
            const float q = trow[m] + (axis ? cpy(m) : cpx(m));
            const float* lr = s_li + m * NK;
#pragma unroll
            for (int k = 0; k < NK; k++) acc[k] = fmaf(lr[k], q, acc[k]);
        }
#pragma unroll
        for (int kp = 0; kp < 14; kp++)
            hilo(acc[2*kp], acc[2*kp+1], s_ch[tid][kp], s_cl[tid][kp]);
        s_ch[tid][14] = 0; s_ch[tid][15] = 0;
        s_cl[tid][14] = 0; s_cl[tid][15] = 0;
    } else {
        // ---- U build: thread = pixel tid-128 ----
        const int px  = tid - 128;
        const int pid = blockIdx.x * PXB + px;
        const int h = pid / OUT_W;
        const int w = pid - h * OUT_W;
        const float gx = g_grid.g[w];
        const float gy = g_grid.g[192 + h];
        float u[NK];
#pragma unroll
        for (int n = 0; n < NCP; n++) {
            const float dx = gx - cpx(n);
            const float dy = gy - cpy(n);
            const float d2 = dx * dx + dy * dy;
            u[n] = (d2 == 0.0f) ? 0.0f : d2 * __log2f(d2);
        }
        u[25] = 1.0f; u[26] = gx; u[27] = gy;
#pragma unroll
        for (int kp = 0; kp < 14; kp++)
            hilo(u[2*kp], u[2*kp+1], s_uh[px][kp], s_ul[px][kp]);
        s_uh[px][14] = 0; s_uh[px][15] = 0;
        s_ul[px][14] = 0; s_ul[px][15] = 0;
    }
    __syncthreads();

    // ---- MMA: warp = 16 px x 128 n (16 n-tiles), 4 k-chunks, 3 accum sets ----
    const int g4  = lid >> 2;     // 0..7
    const int tig = lid & 3;      // 0..3
    const int r0 = wid * 16 + g4;
    const int r1 = r0 + 8;

    uint32_t ah[8], al[8];        // [chunk*2 + {a0,a1}]
#pragma unroll
    for (int c = 0; c < 4; c++) {
        ah[2*c]   = s_uh[r0][4*c + tig];
        ah[2*c+1] = s_uh[r1][4*c + tig];
        al[2*c]   = s_ul[r0][4*c + tig];
        al[2*c+1] = s_ul[r1][4*c + tig];
    }

    const int pxw = blockIdx.x * PXB + wid * 16;
#pragma unroll
    for (int nt = 0; nt < 16; nt++) {
        const int n = nt * 8 + g4;
        uint32_t bh[4], bl[4];
#pragma unroll
        for (int c = 0; c < 4; c++) {
            bh[c] = s_ch[n][4*c + tig];
            bl[c] = s_cl[n][4*c + tig];
        }
        // 3 independent accumulator sets (one per pass): chain depth 4 each
        float e0 = 0.f, e1 = 0.f, e2 = 0.f, e3 = 0.f;   // hi*hi
        float f0 = 0.f, f1 = 0.f, f2 = 0.f, f3 = 0.f;   // hi*lo
        float g0 = 0.f, g1 = 0.f, g2 = 0.f, g3 = 0.f;   // lo*hi
#pragma unroll
        for (int c = 0; c < 4; c++) {
            mma16n8k8(e0, e1, e2, e3, ah[2*c], ah[2*c+1], bh[c]);
            mma16n8k8(f0, f1, f2, f3, ah[2*c], ah[2*c+1], bl[c]);
            mma16n8k8(g0, g1, g2, g3, al[2*c], al[2*c+1], bh[c]);
        }
        const float d0 = e0 + f0 + g0;
        const float d1 = e1 + f1 + g1;
        const float d2 = e2 + f2 + g2;
        const float d3 = e3 + f3 + g3;

        const int bg = nt * 4 + tig;          // batch
        float2* o = out + (size_t)bg * NPX + pxw;
        o[g4]     = make_float2(d0, d1);
        o[g4 + 8] = make_float2(d2, d3);
    }
}

// ---------------------------------------------------------------------------
extern "C" void kernel_launch(void* const* d_in, const int* in_sizes, int n_in,
                              void* d_out, int out_size) {
    const float* theta = (const float*)d_in[0];
    (void)in_sizes; (void)n_in; (void)out_size;

    tps_mma_kernel<<<NPX / PXB, NTHR>>>(theta, (float2*)d_out);
}

// round 15
// speedup vs baseline: 1.6933x; 1.6933x over previous
#include <cuda_runtime.h>
#include <cuda_fp16.h>
#include <cstdint>

// TpsGridGen: theta (64,50) -> grid (64,256,192,2) fp32
// R15: mma.sync.m16n8k16 (half the MMA instrs of k8), conflict-free padded
// fragment smem (17-word rows), warp = 32 px (2 m-tiles) x 128 n.
// Block 128 thr, PXB 128, grid 384. fp16 hi/lo 3-pass, serial f32 accum.

#define OUT_H 256
#define OUT_W 192
#define NPX   (OUT_H * OUT_W)
#define NCP   25
#define NK    28
#define PXB   128
#define NTHR  128

__host__ __device__ constexpr float cpx(int n) { return 0.5f * (float)(n / 5) - 1.0f; }
__host__ __device__ constexpr float cpy(int n) { return 0.5f * (float)(n % 5) - 1.0f; }

// ---------------------------------------------------------------------------
// Compile-time inv(L), transposed to [m][k], RBF rows (k<25) pre-scaled by ln2
// ---------------------------------------------------------------------------
constexpr double cfabs(double x) { return x < 0.0 ? -x : x; }

constexpr double clog(double x) {
    int e = 0;
    while (x >= 1.4142135623730951) { x *= 0.5; e++; }
    while (x <  0.7071067811865476) { x *= 2.0; e--; }
    double t = (x - 1.0) / (x + 1.0), t2 = t * t, p = t, s = 0.0;
    for (int k = 0; k < 27; k++) { s += p / (double)(2 * k + 1); p *= t2; }
    return 2.0 * s + (double)e * 0.6931471805599453094172321214581766;
}

struct alignas(16) TPSLiS { float v[NCP][NK]; };   // [m][k]

constexpr TPSLiS make_lis() {
    const double ax[5] = {-1.0, -0.5, 0.0, 0.5, 1.0};
    double PX[NCP] = {}, PY[NCP] = {};
    for (int i = 0; i < 5; i++)
        for (int j = 0; j < 5; j++) { PX[i*5+j] = ax[i]; PY[i*5+j] = ax[j]; }

    double a[28][56] = {};
    for (int i = 0; i < 25; i++)
        for (int j = 0; j < 25; j++)
            if (i != j) {
                double dx = PX[i]-PX[j], dy = PY[i]-PY[j];
                double d2 = dx*dx + dy*dy;
                a[i][j] = d2 * clog(d2);
            }
    for (int i = 0; i < 25; i++) {
        a[i][25] = 1.0; a[i][26] = PX[i]; a[i][27] = PY[i];
        a[25][i] = 1.0; a[26][i] = PX[i]; a[27][i] = PY[i];
    }
    for (int i = 0; i < 28; i++) a[i][28+i] = 1.0;

    for (int k = 0; k < 28; k++) {
        int piv = k; double best = cfabs(a[k][k]);
        for (int i = k+1; i < 28; i++) {
            double v = cfabs(a[i][k]);
            if (v > best) { best = v; piv = i; }
        }
        if (piv != k)
            for (int j = 0; j < 56; j++) {
                double t = a[k][j]; a[k][j] = a[piv][j]; a[piv][j] = t;
            }
        double inv = 1.0 / a[k][k];
        for (int j = 0; j < 56; j++) a[k][j] *= inv;
        for (int i = 0; i < 28; i++) {
            if (i == k) continue;
            double f = a[i][k];
            if (f != 0.0)
                for (int j = 0; j < 56; j++) a[i][j] -= f * a[k][j];
        }
    }
    const double LN2 = 0.6931471805599453094172321214581766;
    TPSLiS r{};
    for (int m = 0; m < NCP; m++)
        for (int k = 0; k < NK; k++)
            r.v[m][k] = (float)(((k < 25) ? LN2 : 1.0) * a[k][28 + m]);
    return r;
}

__device__ const TPSLiS g_lis = make_lis();

// Compile-time linspace tables (numpy fp64 semantics, endpoint exact).
struct alignas(16) GridTab { float g[448]; };   // [0..191]=gx, [192..447]=gy

constexpr GridTab make_grid() {
    GridTab r{};
    for (int w = 0; w < OUT_W; w++)
        r.g[w] = (float)(-1.0 + (double)w * (2.0 / (double)(OUT_W - 1)));
    r.g[OUT_W - 1] = 1.0f;
    for (int h = 0; h < OUT_H; h++)
        r.g[192 + h] = (float)(-1.0 + (double)h * (2.0 / (double)(OUT_H - 1)));
    r.g[192 + OUT_H - 1] = 1.0f;
    return r;
}

__device__ const GridTab g_grid = make_grid();

// ---------------------------------------------------------------------------
__device__ __forceinline__ uint32_t h2bits(__half2 h) {
    return *reinterpret_cast<uint32_t*>(&h);
}

__device__ __forceinline__ void hilo(float v0, float v1, uint32_t& hi, uint32_t& lo) {
    __half2 h = __floats2half2_rn(v0, v1);
    float r0 = v0 - __low2float(h);
    float r1 = v1 - __high2float(h);
    hi = h2bits(h);
    lo = h2bits(__floats2half2_rn(r0, r1));
}

__device__ __forceinline__ void mma16n8k16(float& d0, float& d1, float& d2, float& d3,
                                           uint32_t a0, uint32_t a1, uint32_t a2,
                                           uint32_t a3, uint32_t b0, uint32_t b1) {
    asm("mma.sync.aligned.m16n8k16.row.col.f32.f16.f16.f32 "
        "{%0,%1,%2,%3},{%4,%5,%6,%7},{%8,%9},{%0,%1,%2,%3};"
        : "+f"(d0), "+f"(d1), "+f"(d2), "+f"(d3)
        : "r"(a0), "r"(a1), "r"(a2), "r"(a3), "r"(b0), "r"(b1));
}

// ---------------------------------------------------------------------------
// Kernel. grid 384, block 128. Block = 128 px x 64 batches (128 n-rows).
// Warp = 32 px (2 m-tiles) x 128 n (16 n-tiles).
// Fragment smem rows padded to 17 words (68B) -> conflict-free.
// ---------------------------------------------------------------------------
__global__ __launch_bounds__(NTHR) void tps_mma_kernel(
    const float* __restrict__ theta, float2* __restrict__ out) {

    __shared__ __align__(16) float s_li[NCP * NK];           // 2.8 KB
    __shared__ uint32_t s_uh[PXB][17], s_ul[PXB][17];        // 17.4 KB
    __shared__ uint32_t s_ch[128][17], s_cl[128][17];        // 17.4 KB

    const int tid = threadIdx.x;
    const int wid = tid >> 5;
    const int lid = tid & 31;

    // ---- Stage Li ----
    {
        const float4* ls = (const float4*)&g_lis;
        for (int i = tid; i < 175; i += NTHR) ((float4*)s_li)[i] = ls[i];
    }
    __syncthreads();

    // ---- Phase A: thread = n-row (n = 2b+axis), theta from L2 ----
    {
        const int b    = tid >> 1;
        const int axis = tid & 1;
        const float* trow = theta + b * 50 + axis * NCP;
        float acc[NK];
#pragma unroll
        for (int k = 0; k < NK; k++) acc[k] = 0.f;
#pragma unroll
        for (int m = 0; m < NCP; m++) {
            const float q = trow[m] + (axis ? cpy(m) : cpx(m));
            const float* lr = s_li + m * NK;
#pragma unroll
            for (int k = 0; k < NK; k++) acc[k] = fmaf(lr[k], q, acc[k]);
        }
#pragma unroll
        for (int kp = 0; kp < 14; kp++)
            hilo(acc[2*kp], acc[2*kp+1], s_ch[tid][kp], s_cl[tid][kp]);
        s_ch[tid][14] = 0; s_ch[tid][15] = 0;
        s_cl[tid][14] = 0; s_cl[tid][15] = 0;
    }

    // ---- U build: thread = pixel ----
    {
        const int px  = tid;
        const int pid = blockIdx.x * PXB + px;
        const int h = pid / OUT_W;
        const int w = pid - h * OUT_W;
        const float gx = g_grid.g[w];
        const float gy = g_grid.g[192 + h];
        float u[NK];
#pragma unroll
        for (int n = 0; n < NCP; n++) {
            const float dx = gx - cpx(n);
            const float dy = gy - cpy(n);
            const float d2 = dx * dx + dy * dy;
            u[n] = (d2 == 0.0f) ? 0.0f : d2 * __log2f(d2);
        }
        u[25] = 1.0f; u[26] = gx; u[27] = gy;
#pragma unroll
        for (int kp = 0; kp < 14; kp++)
            hilo(u[2*kp], u[2*kp+1], s_uh[px][kp], s_ul[px][kp]);
        s_uh[px][14] = 0; s_uh[px][15] = 0;
        s_ul[px][14] = 0; s_ul[px][15] = 0;
    }
    __syncthreads();

    // ---- MMA: warp = 32 px (2 mt) x 128 n (16 nt), 2 k16-chunks, 3 passes ----
    const int g4  = lid >> 2;     // 0..7
    const int tig = lid & 3;      // 0..3

    // A fragments: [mt][k16chunk*4 + reg]; k16 regs = {r0 kpA, r1 kpA, r0 kpB, r1 kpB}
    uint32_t ah[2][8], al[2][8];
#pragma unroll
    for (int mt = 0; mt < 2; mt++) {
        const int r0 = wid * 32 + mt * 16 + g4;
        const int r1 = r0 + 8;
#pragma unroll
        for (int c16 = 0; c16 < 2; c16++) {
            const int kpA = 8 * c16 + tig;
            const int kpB = 8 * c16 + 4 + tig;
            ah[mt][4*c16+0] = s_uh[r0][kpA];
            ah[mt][4*c16+1] = s_uh[r1][kpA];
            ah[mt][4*c16+2] = s_uh[r0][kpB];
            ah[mt][4*c16+3] = s_uh[r1][kpB];
            al[mt][4*c16+0] = s_ul[r0][kpA];
            al[mt][4*c16+1] = s_ul[r1][kpA];
            al[mt][4*c16+2] = s_ul[r0][kpB];
            al[mt][4*c16+3] = s_ul[r1][kpB];
        }
    }

    const int pxw = blockIdx.x * PXB + wid * 32;
#pragma unroll
    for (int nt = 0; nt < 16; nt++) {
        const int n = nt * 8 + g4;
        // B fragments: chunk c16: {b0,b1} = {kp 8c16+tig, kp 8c16+4+tig}
        uint32_t bh[4], bl[4];
        bh[0] = s_ch[n][tig];      bh[1] = s_ch[n][4 + tig];
        bh[2] = s_ch[n][8 + tig];  bh[3] = s_ch[n][12 + tig];
        bl[0] = s_cl[n][tig];      bl[1] = s_cl[n][4 + tig];
        bl[2] = s_cl[n][8 + tig];  bl[3] = s_cl[n][12 + tig];

        const int bg = nt * 4 + tig;          // batch
        float2* o = out + (size_t)bg * NPX + pxw;
#pragma unroll
        for (int mt = 0; mt < 2; mt++) {
            float d0 = 0.f, d1 = 0.f, d2 = 0.f, d3 = 0.f;
            // chunk16 0 (k0..15): hi*hi, hi*lo, lo*hi
            mma16n8k16(d0,d1,d2,d3, ah[mt][0],ah[mt][1],ah[mt][2],ah[mt][3], bh[0],bh[1]);
            mma16n8k16(d0,d1,d2,d3, ah[mt][0],ah[mt][1],ah[mt][2],ah[mt][3], bl[0],bl[1]);
            mma16n8k16(d0,d1,d2,d3, al[mt][0],al[mt][1],al[mt][2],al[mt][3], bh[0],bh[1]);
            // chunk16 1 (k16..31)
            mma16n8k16(d0,d1,d2,d3, ah[mt][4],ah[mt][5],ah[mt][6],ah[mt][7], bh[2],bh[3]);
            mma16n8k16(d0,d1,d2,d3, ah[mt][4],ah[mt][5],ah[mt][6],ah[mt][7], bl[2],bl[3]);
            mma16n8k16(d0,d1,d2,d3, al[mt][4],al[mt][5],al[mt][6],al[mt][7], bh[2],bh[3]);

            o[mt * 16 + g4]     = make_float2(d0, d1);
            o[mt * 16 + g4 + 8] = make_float2(d2, d3);
        }
    }
}

// ---------------------------------------------------------------------------
extern "C" void kernel_launch(void* const* d_in, const int* in_sizes, int n_in,
                              void* d_out, int out_size) {
    const float* theta = (const float*)d_in[0];
    (void)in_sizes; (void)n_in; (void)out_size;

    tps_mma_kernel<<<NPX / PXB, NTHR>>>(theta, (float2*)d_out);
}